// round 8
// baseline (speedup 1.0000x reference)
#include <cuda_runtime.h>
#include <math.h>

typedef unsigned long long ull;

#define BATCH 256
#define SEQT  512
#define EMBD  300
#define HID   150
#define G4    600   // 4*HID
#define SMW   92    // Whh cols in smem (92 mod 32 = 28, gcd 4 -> conflict-free float4)
#define NRW   58    // Whh cols in registers = 29 u64
#define HS    152   // padded h/c/act stride (16B-aligned)

#define FMA2(d, a, b) asm("fma.rn.f32x2 %0, %1, %2, %3;" : "=l"(d) : "l"(a), "l"(b), "l"(d))

__device__ __forceinline__ float sig_f(float x)  { return __fdividef(1.f, 1.f + __expf(-x)); }
__device__ __forceinline__ float tanh_f(float x) { return 1.f - __fdividef(2.f, __expf(2.f * x) + 1.f); }

// ---------------- scratch (static device globals; no allocation) ----------------
__device__ float g_e [(size_t)BATCH*SEQT*EMBD];
__device__ float g_xp[(size_t)BATCH*SEQT*G4];
__device__ float g_sa[(size_t)BATCH*SEQT*HID];
__device__ float g_sb[(size_t)BATCH*SEQT*HID];
__device__ float g_hn[BATCH*HID];

// ---------------- profiling-alignment dummy (shifts ncu -s 5 window onto lstm_k) ----------------
__global__ void align_k() {
    if (threadIdx.x < HID) g_hn[threadIdx.x] = 0.f;   // overwritten by lstm_k later
}

// ---------------- embedding gather (x is int32 on device) ----------------
__global__ void embed_k(const int* __restrict__ x, const float* __restrict__ emb) {
    int idx = blockIdx.x * blockDim.x + threadIdx.x;
    const int total = BATCH * SEQT * (EMBD / 4);
    if (idx >= total) return;
    int bt = idx / (EMBD / 4);
    int d4 = (idx - bt * (EMBD / 4)) * 4;
    int row = x[bt];
    const float4 v = *(const float4*)(emb + (size_t)row * EMBD + d4);
    *(float4*)(g_e + (size_t)bt * EMBD + d4) = v;
}

// ---------------- x-projection GEMM (round-5 version: best measured) ----------------
__global__ void __launch_bounds__(256) gemm_xproj(
    const float* __restrict__ A, int K,
    const float* __restrict__ W,
    const float* __restrict__ b1,
    const float* __restrict__ b2,
    float* __restrict__ C) {
    __shared__ float As[16][132];
    __shared__ float Bs[16][132];
    const int tid = threadIdx.x;
    const int m0 = blockIdx.x * 128, n0 = blockIdx.y * 128;
    const int tx = tid & 15, ty = tid >> 4;
    const int lr = tid >> 1, lk = (tid & 1) * 8;

    ull acc2[8][4];
#pragma unroll
    for (int i = 0; i < 8; i++)
#pragma unroll
        for (int j = 0; j < 4; j++) acc2[i][j] = 0ull;

    const float* Ap = A + (size_t)(m0 + lr) * K;
    const int nrow = n0 + lr;
    const float* Wp = W + (size_t)nrow * K;
    const bool wok = nrow < G4;
    const int nt = (K + 15) / 16;

    for (int kt = 0; kt < nt; kt++) {
        const int k0 = kt * 16;
#pragma unroll
        for (int c = 0; c < 4; c++) {
            int k = k0 + lk + 2 * c;
            float2 av = (k < K) ? *(const float2*)(Ap + k) : make_float2(0.f, 0.f);
            float2 wv = (wok && k < K) ? *(const float2*)(Wp + k) : make_float2(0.f, 0.f);
            As[lk + 2 * c][lr]     = av.x;
            As[lk + 2 * c + 1][lr] = av.y;
            Bs[lk + 2 * c][lr]     = wv.x;
            Bs[lk + 2 * c + 1][lr] = wv.y;
        }
        __syncthreads();
#pragma unroll
        for (int kk = 0; kk < 16; kk++) {
            float4 al = *(const float4*)&As[kk][ty * 4];
            float4 ah = *(const float4*)&As[kk][64 + ty * 4];
            ulonglong2 bl = *(const ulonglong2*)&Bs[kk][tx * 4];
            ulonglong2 bh = *(const ulonglong2*)&Bs[kk][64 + tx * 4];
            float a_s[8] = {al.x, al.y, al.z, al.w, ah.x, ah.y, ah.z, ah.w};
#pragma unroll
            for (int i = 0; i < 8; i++) {
                float2 t = make_float2(a_s[i], a_s[i]);
                ull ad = *(ull*)&t;
                FMA2(acc2[i][0], ad, bl.x);
                FMA2(acc2[i][1], ad, bl.y);
                FMA2(acc2[i][2], ad, bh.x);
                FMA2(acc2[i][3], ad, bh.y);
            }
        }
        __syncthreads();
    }
#pragma unroll
    for (int i = 0; i < 8; i++) {
        int m = m0 + ((i < 4) ? ty * 4 + i : 64 + ty * 4 + (i - 4));
        float* Cr = C + (size_t)m * G4;
#pragma unroll
        for (int j2 = 0; j2 < 4; j2++) {
            float2 p = *(float2*)&acc2[i][j2];
            int nn = n0 + ((j2 < 2) ? tx * 4 + 2 * j2 : 64 + tx * 4 + 2 * (j2 - 2));
            if (nn < G4)     Cr[nn]     = p.x + b1[nn]     + b2[nn];
            if (nn + 1 < G4) Cr[nn + 1] = p.y + b1[nn + 1] + b2[nn + 1];
        }
    }
}

// ---------------- LSTM layer: ONE CTA per 2 batch elements ----------------
// Thread r<600 owns gate row r for both batches. W cols [0,92) smem (220.8KB),
// cols [92,150) in 29 u64 registers. xg loads double-buffered one step ahead.
__global__ void __launch_bounds__(608, 1) lstm_k(
    const float* __restrict__ xp, const float* __restrict__ Whh,
    const int* __restrict__ lengths,
    float* __restrict__ seq_out, float* __restrict__ hn_out)
{
    extern __shared__ float sm[];
    float* Wsh = sm;                    // 600*SMW
    float* h_s = Wsh + 600 * SMW;       // 2*HS
    float* c_s = h_s + 2 * HS;          // 2*HS
    float* act = c_s + 2 * HS;          // 8*HS : [b][gate][j]

    const int tid = threadIdx.x;
    const int b0  = blockIdx.x * 2;

    for (int idx = tid; idx < 600 * SMW; idx += 608) {
        int r = idx / SMW, k = idx - r * SMW;
        Wsh[idx] = Whh[(size_t)r * 150 + k];
    }
    for (int idx = tid; idx < 4 * HS; idx += 608) h_s[idx] = 0.f;  // h_s + c_s

    const int r = (tid < 600) ? tid : 0;
    // register part: cols 92..149 as 29 packed u64 pairs (8B-aligned: 150r+92 even)
    ull wr2[29];
    const float* wg = Whh + (size_t)r * 150 + SMW;
#pragma unroll
    for (int i = 0; i < 29; i++)
        wr2[i] = (tid < 600) ? *(const ull*)(wg + 2 * i) : 0ull;

    const int gate = r / 150;
    const int jrow = r - gate * 150;
    const float* wp = Wsh + r * SMW;
    const float* xpA = xp + ((size_t)b0 * SEQT) * G4 + r;
    const float* xpB = xp + ((size_t)(b0 + 1) * SEQT) * G4 + r;

    int ub = 0, uj = 0, mylen = 0;
    if (tid < 300) {
        ub = tid / 150; uj = tid - ub * 150;
        mylen = lengths[b0 + ub];
    }

    // prefetch t=0
    float xgA = (tid < 600) ? xpA[0] : 0.f;
    float xgB = (tid < 600) ? xpB[0] : 0.f;

    __syncthreads();

    for (int t = 0; t < SEQT; t++) {
        if (tid < 600) {
            // prefetch t+1 (latency hidden under the dot product below)
            float nxA = xgA, nxB = xgB;
            if (t + 1 < SEQT) {
                nxA = xpA[(size_t)(t + 1) * G4];
                nxB = xpB[(size_t)(t + 1) * G4];
            }

            ull accA = 0ull, accB = 0ull;
            const float* hA = h_s;
            const float* hB = h_s + HS;
            // smem W: cols [0,92)
#pragma unroll
            for (int g = 0; g < 23; g++) {
                const int k = 4 * g;
                ulonglong2 w2 = *(const ulonglong2*)(wp + k);
                ulonglong2 a2 = *(const ulonglong2*)(hA + k);
                ulonglong2 b2 = *(const ulonglong2*)(hB + k);
                FMA2(accA, w2.x, a2.x); FMA2(accA, w2.y, a2.y);
                FMA2(accB, w2.x, b2.x); FMA2(accB, w2.y, b2.y);
            }
            // register W: cols [92,148)
#pragma unroll
            for (int c = 0; c < 14; c++) {
                const int k = SMW + 4 * c;
                ulonglong2 a2 = *(const ulonglong2*)(hA + k);
                ulonglong2 b2 = *(const ulonglong2*)(hB + k);
                FMA2(accA, wr2[2 * c], a2.x); FMA2(accA, wr2[2 * c + 1], a2.y);
                FMA2(accB, wr2[2 * c], b2.x); FMA2(accB, wr2[2 * c + 1], b2.y);
            }
            {   // cols 148,149
                ull a1 = *(const ull*)(hA + 148);
                ull b1 = *(const ull*)(hB + 148);
                FMA2(accA, wr2[28], a1); FMA2(accB, wr2[28], b1);
            }
            float2 fA = *(float2*)&accA;
            float2 fB = *(float2*)&accB;
            float preA = fA.x + fA.y + xgA;
            float preB = fB.x + fB.y + xgB;
            float vA, vB;
            if (gate == 2) { vA = tanh_f(preA); vB = tanh_f(preB); }
            else           { vA = sig_f(preA);  vB = sig_f(preB);  }
            act[(0 * 4 + gate) * HS + jrow] = vA;
            act[(1 * 4 + gate) * HS + jrow] = vB;
            xgA = nxA; xgB = nxB;
        }
        __syncthreads();
        if (tid < 300) {
            float gi = act[(ub * 4 + 0) * HS + uj];
            float gf = act[(ub * 4 + 1) * HS + uj];
            float gg = act[(ub * 4 + 2) * HS + uj];
            float go = act[(ub * 4 + 3) * HS + uj];
            float c  = c_s[ub * HS + uj];
            float cn = fmaf(gf, c, gi * gg);
            float hv = go * tanh_f(cn);
            bool msk = t < mylen;
            seq_out[((size_t)(b0 + ub) * SEQT + t) * HID + uj] = msk ? hv : 0.f;
            if (msk) {
                c_s[ub * HS + uj] = cn;
                h_s[ub * HS + uj] = hv;
            }
        }
        __syncthreads();
    }

    if (tid < 300)
        hn_out[(b0 + ub) * HID + uj] = h_s[ub * HS + uj];
}

// ---------------- FC head ----------------
__global__ void fc_k(const float* __restrict__ hn, const float* __restrict__ w1,
                     const float* __restrict__ b1v, const float* __restrict__ w2,
                     const float* __restrict__ b2v, float* __restrict__ out) {
    __shared__ float red[256];
    int b = blockIdx.x, tid = threadIdx.x;
    float part = 0.f;
    if (tid < HID) {
        float acc = 0.f;
        const float* hr = hn + b * HID;
        const float* wrw = w1 + tid * HID;
        for (int k = 0; k < HID; k++) acc = fmaf(wrw[k], hr[k], acc);
        float z = fmaxf(acc + b1v[tid], 0.f);
        part = z * w2[tid];
    }
    red[tid] = part;
    __syncthreads();
    for (int s = 128; s > 0; s >>= 1) {
        if (tid < s) red[tid] += red[tid + s];
        __syncthreads();
    }
    if (tid == 0) out[b] = red[0] + b2v[0];
}

// ---------------- launch ----------------
extern "C" void kernel_launch(void* const* d_in, const int* in_sizes, int n_in,
                              void* d_out, int out_size) {
    const int* x   = (const int*)d_in[0];
    const int* len = (const int*)d_in[1];
    const float* emb = (const float*)d_in[2];
    const float *Wih[4], *Whh[4], *bih[4], *bhh[4];
    for (int l = 0; l < 4; l++) {
        Wih[l] = (const float*)d_in[3 + 4 * l];
        Whh[l] = (const float*)d_in[4 + 4 * l];
        bih[l] = (const float*)d_in[5 + 4 * l];
        bhh[l] = (const float*)d_in[6 + 4 * l];
    }
    const float* fc1w = (const float*)d_in[19];
    const float* fc1b = (const float*)d_in[20];
    const float* fc2w = (const float*)d_in[21];
    const float* fc2b = (const float*)d_in[22];
    float* out = (float*)d_out;

    float *pe, *pxp, *psa, *psb, *phn;
    cudaGetSymbolAddress((void**)&pe,  g_e);
    cudaGetSymbolAddress((void**)&pxp, g_xp);
    cudaGetSymbolAddress((void**)&psa, g_sa);
    cudaGetSymbolAddress((void**)&psb, g_sb);
    cudaGetSymbolAddress((void**)&phn, g_hn);

    const int SMEM = (600 * SMW + 2 * HS + 2 * HS + 8 * HS) * 4;  // 228096 B
    cudaFuncSetAttribute(lstm_k, cudaFuncAttributeMaxDynamicSharedMemorySize, SMEM);

    // launch order matters for ncu (-s 5 -c 1): index 5 must be lstm_k (layer 2, K=150 steady state)
    align_k<<<1, 128>>>();                                      // idx 0
    embed_k<<<38400, 256>>>(x, emb);                            // idx 1

    dim3 gg(1024, 5);
    gemm_xproj<<<gg, 256>>>(pe,  EMBD, Wih[0], bih[0], bhh[0], pxp);   // idx 2
    lstm_k<<<128, 608, SMEM>>>(pxp, Whh[0], len, psa, phn);            // idx 3

    gemm_xproj<<<gg, 256>>>(psa, HID,  Wih[1], bih[1], bhh[1], pxp);   // idx 4
    lstm_k<<<128, 608, SMEM>>>(pxp, Whh[1], len, psb, phn);            // idx 5  <- profiled

    gemm_xproj<<<gg, 256>>>(psb, HID,  Wih[2], bih[2], bhh[2], pxp);
    lstm_k<<<128, 608, SMEM>>>(pxp, Whh[2], len, psa, phn);

    gemm_xproj<<<gg, 256>>>(psa, HID,  Wih[3], bih[3], bhh[3], pxp);
    lstm_k<<<128, 608, SMEM>>>(pxp, Whh[3], len, psb, phn);

    fc_k<<<256, 256>>>(phn, fc1w, fc1b, fc2w, fc2b, out);
}

// round 9
// speedup vs baseline: 1.0949x; 1.0949x over previous
#include <cuda_runtime.h>
#include <math.h>

typedef unsigned long long ull;

#define BATCH 256
#define SEQT  512
#define EMBD  300
#define HID   150
#define G4    600   // 4*HID
#define SMW   92    // Whh cols in smem (stride 92 words -> exactly-4wf LDS.128)
#define HS    152   // padded h stride (16B-aligned)
#define PS    152   // prod stride

#define FMA2(d, a, b) asm("fma.rn.f32x2 %0, %1, %2, %3;" : "=l"(d) : "l"(a), "l"(b), "l"(d))

__device__ __forceinline__ float sig_f(float x)  { return __fdividef(1.f, 1.f + __expf(-x)); }
__device__ __forceinline__ float tanh_f(float x) { return 1.f - __fdividef(2.f, __expf(2.f * x) + 1.f); }

// ---------------- scratch (static device globals; no allocation) ----------------
__device__ float g_e [(size_t)BATCH*SEQT*EMBD];
__device__ float g_xp[(size_t)BATCH*SEQT*G4];
__device__ float g_sa[(size_t)BATCH*SEQT*HID];
__device__ float g_sb[(size_t)BATCH*SEQT*HID];
__device__ float g_hn[BATCH*HID];

// ---------------- profiling-alignment dummy (keeps ncu -s 5 window on lstm_k) ----------------
__global__ void align_k() {
    if (threadIdx.x < HID) g_hn[threadIdx.x] = 0.f;   // overwritten by lstm_k later
}

// ---------------- embedding gather (x is int32 on device) ----------------
__global__ void embed_k(const int* __restrict__ x, const float* __restrict__ emb) {
    int idx = blockIdx.x * blockDim.x + threadIdx.x;
    const int total = BATCH * SEQT * (EMBD / 4);
    if (idx >= total) return;
    int bt = idx / (EMBD / 4);
    int d4 = (idx - bt * (EMBD / 4)) * 4;
    int row = x[bt];
    const float4 v = *(const float4*)(emb + (size_t)row * EMBD + d4);
    *(float4*)(g_e + (size_t)bt * EMBD + d4) = v;
}

// ---------------- x-projection GEMM (round-5 version: best measured) ----------------
__global__ void __launch_bounds__(256) gemm_xproj(
    const float* __restrict__ A, int K,
    const float* __restrict__ W,
    const float* __restrict__ b1,
    const float* __restrict__ b2,
    float* __restrict__ C) {
    __shared__ float As[16][132];
    __shared__ float Bs[16][132];
    const int tid = threadIdx.x;
    const int m0 = blockIdx.x * 128, n0 = blockIdx.y * 128;
    const int tx = tid & 15, ty = tid >> 4;
    const int lr = tid >> 1, lk = (tid & 1) * 8;

    ull acc2[8][4];
#pragma unroll
    for (int i = 0; i < 8; i++)
#pragma unroll
        for (int j = 0; j < 4; j++) acc2[i][j] = 0ull;

    const float* Ap = A + (size_t)(m0 + lr) * K;
    const int nrow = n0 + lr;
    const float* Wp = W + (size_t)nrow * K;
    const bool wok = nrow < G4;
    const int nt = (K + 15) / 16;

    for (int kt = 0; kt < nt; kt++) {
        const int k0 = kt * 16;
#pragma unroll
        for (int c = 0; c < 4; c++) {
            int k = k0 + lk + 2 * c;
            float2 av = (k < K) ? *(const float2*)(Ap + k) : make_float2(0.f, 0.f);
            float2 wv = (wok && k < K) ? *(const float2*)(Wp + k) : make_float2(0.f, 0.f);
            As[lk + 2 * c][lr]     = av.x;
            As[lk + 2 * c + 1][lr] = av.y;
            Bs[lk + 2 * c][lr]     = wv.x;
            Bs[lk + 2 * c + 1][lr] = wv.y;
        }
        __syncthreads();
#pragma unroll
        for (int kk = 0; kk < 16; kk++) {
            float4 al = *(const float4*)&As[kk][ty * 4];
            float4 ah = *(const float4*)&As[kk][64 + ty * 4];
            ulonglong2 bl = *(const ulonglong2*)&Bs[kk][tx * 4];
            ulonglong2 bh = *(const ulonglong2*)&Bs[kk][64 + tx * 4];
            float a_s[8] = {al.x, al.y, al.z, al.w, ah.x, ah.y, ah.z, ah.w};
#pragma unroll
            for (int i = 0; i < 8; i++) {
                float2 t = make_float2(a_s[i], a_s[i]);
                ull ad = *(ull*)&t;
                FMA2(acc2[i][0], ad, bl.x);
                FMA2(acc2[i][1], ad, bl.y);
                FMA2(acc2[i][2], ad, bh.x);
                FMA2(acc2[i][3], ad, bh.y);
            }
        }
        __syncthreads();
    }
#pragma unroll
    for (int i = 0; i < 8; i++) {
        int m = m0 + ((i < 4) ? ty * 4 + i : 64 + ty * 4 + (i - 4));
        float* Cr = C + (size_t)m * G4;
#pragma unroll
        for (int j2 = 0; j2 < 4; j2++) {
            float2 p = *(float2*)&acc2[i][j2];
            int nn = n0 + ((j2 < 2) ? tx * 4 + 2 * j2 : 64 + tx * 4 + 2 * (j2 - 2));
            if (nn < G4)     Cr[nn]     = p.x + b1[nn]     + b2[nn];
            if (nn + 1 < G4) Cr[nn + 1] = p.y + b1[nn + 1] + b2[nn + 1];
        }
    }
}

// ---------------- LSTM layer: ONE CTA per 2 batches, 320 threads ----------------
// Thread (p,j): p=0 owns gate rows {j (i), 300+j (g)}, p=1 owns {150+j (f), 450+j (o)},
// each for BOTH batches. W cols [0,92) smem, [92,150) in 2x29 u64 regs.
// c lives in p=1 registers; h double-buffered in smem; i*g handed off via prod[].
__global__ void __launch_bounds__(320, 1) lstm_k(
    const float* __restrict__ xp, const float* __restrict__ Whh,
    const int* __restrict__ lengths,
    float* __restrict__ seq_out, float* __restrict__ hn_out)
{
    extern __shared__ float sm[];
    float* Wsh  = sm;                    // 600*SMW
    float* hbuf = Wsh + 600 * SMW;       // 2 buffers x 2 batches x HS
    float* prod = hbuf + 4 * HS;         // 2*PS

    const int tid = threadIdx.x;
    const int b0  = blockIdx.x * 2;
    const int p   = tid / 160;           // warps 0-4: p=0, warps 5-9: p=1
    const int j   = tid - p * 160;
    const bool on = (j < 150);

    for (int idx = tid; idx < 600 * SMW; idx += 320) {
        int r = idx / SMW, k = idx - r * SMW;
        Wsh[idx] = Whh[(size_t)r * 150 + k];
    }
    for (int idx = tid; idx < 4 * HS; idx += 320) hbuf[idx] = 0.f;

    const int row0 = p * 150 + ((j < 150) ? j : 0);   // i or f
    const int row1 = row0 + 300;                      // g or o
    ull w0r[29], w1r[29];
    {
        const float* g0 = Whh + (size_t)row0 * 150 + SMW;
        const float* g1 = Whh + (size_t)row1 * 150 + SMW;
#pragma unroll
        for (int i = 0; i < 29; i++) {
            w0r[i] = on ? *(const ull*)(g0 + 2 * i) : 0ull;
            w1r[i] = on ? *(const ull*)(g1 + 2 * i) : 0ull;
        }
    }
    const float* wp0 = Wsh + row0 * SMW;
    const float* wp1 = Wsh + row1 * SMW;

    const float* xA = xp + ((size_t)b0 * SEQT) * G4;
    const float* xB = xp + ((size_t)(b0 + 1) * SEQT) * G4;

    const int lenA = lengths[b0], lenB = lengths[b0 + 1];
    float cAr = 0.f, cBr = 0.f, hoA = 0.f, hoB = 0.f;   // p=1 private state
    float fA = 0.f, fB = 0.f, oA = 0.f, oB = 0.f;       // carried across barrier

    // prefetch xg for t=0
    float x0A = 0.f, x1A = 0.f, x0B = 0.f, x1B = 0.f;
    if (on) {
        x0A = xA[row0]; x1A = xA[row1];
        x0B = xB[row0]; x1B = xB[row1];
    }
    __syncthreads();

    for (int t = 0; t < SEQT; t++) {
        const float* hR = hbuf + (t & 1) * (2 * HS);
        float* hW = hbuf + ((t + 1) & 1) * (2 * HS);
        if (on) {
            ull a00 = 0ull, a01 = 0ull, a10 = 0ull, a11 = 0ull;  // (row, batch)
#pragma unroll
            for (int g = 0; g < 23; g++) {
                const int k = 4 * g;
                ulonglong2 hA2 = *(const ulonglong2*)(hR + k);
                ulonglong2 hB2 = *(const ulonglong2*)(hR + HS + k);
                ulonglong2 w0 = *(const ulonglong2*)(wp0 + k);
                ulonglong2 w1 = *(const ulonglong2*)(wp1 + k);
                FMA2(a00, w0.x, hA2.x); FMA2(a00, w0.y, hA2.y);
                FMA2(a01, w0.x, hB2.x); FMA2(a01, w0.y, hB2.y);
                FMA2(a10, w1.x, hA2.x); FMA2(a10, w1.y, hA2.y);
                FMA2(a11, w1.x, hB2.x); FMA2(a11, w1.y, hB2.y);
            }
#pragma unroll
            for (int c = 0; c < 14; c++) {
                const int k = SMW + 4 * c;
                ulonglong2 hA2 = *(const ulonglong2*)(hR + k);
                ulonglong2 hB2 = *(const ulonglong2*)(hR + HS + k);
                FMA2(a00, w0r[2 * c], hA2.x); FMA2(a00, w0r[2 * c + 1], hA2.y);
                FMA2(a01, w0r[2 * c], hB2.x); FMA2(a01, w0r[2 * c + 1], hB2.y);
                FMA2(a10, w1r[2 * c], hA2.x); FMA2(a10, w1r[2 * c + 1], hA2.y);
                FMA2(a11, w1r[2 * c], hB2.x); FMA2(a11, w1r[2 * c + 1], hB2.y);
            }
            {   // cols 148,149
                ull hA1 = *(const ull*)(hR + 148);
                ull hB1 = *(const ull*)(hR + HS + 148);
                FMA2(a00, w0r[28], hA1); FMA2(a01, w0r[28], hB1);
                FMA2(a10, w1r[28], hA1); FMA2(a11, w1r[28], hB1);
            }
            float2 f00 = *(float2*)&a00, f01 = *(float2*)&a01;
            float2 f10 = *(float2*)&a10, f11 = *(float2*)&a11;
            float pre0A = f00.x + f00.y + x0A;
            float pre0B = f01.x + f01.y + x0B;
            float pre1A = f10.x + f10.y + x1A;
            float pre1B = f11.x + f11.y + x1B;
            if (t + 1 < SEQT) {   // prefetch next xg (latency hidden into phase B)
                const size_t o = (size_t)(t + 1) * G4;
                x0A = xA[o + row0]; x1A = xA[o + row1];
                x0B = xB[o + row0]; x1B = xB[o + row1];
            }
            if (p == 0) {
                prod[j]      = sig_f(pre0A) * tanh_f(pre1A);   // i*g, batch A
                prod[PS + j] = sig_f(pre0B) * tanh_f(pre1B);   // i*g, batch B
            } else {
                fA = sig_f(pre0A); fB = sig_f(pre0B);          // f
                oA = sig_f(pre1A); oB = sig_f(pre1B);          // o
            }
        }
        __syncthreads();
        if (on && p == 1) {
            float cnA = fmaf(fA, cAr, prod[j]);
            float cnB = fmaf(fB, cBr, prod[PS + j]);
            float hvA = oA * tanh_f(cnA);
            float hvB = oB * tanh_f(cnB);
            bool mA = t < lenA, mB = t < lenB;
            seq_out[((size_t)b0 * SEQT + t) * HID + j]       = mA ? hvA : 0.f;
            seq_out[((size_t)(b0 + 1) * SEQT + t) * HID + j] = mB ? hvB : 0.f;
            if (mA) { cAr = cnA; hoA = hvA; }
            if (mB) { cBr = cnB; hoB = hvB; }
            hW[j]      = hoA;
            hW[HS + j] = hoB;
        }
        __syncthreads();
    }

    if (on && p == 1) {
        hn_out[b0 * HID + j]       = hoA;
        hn_out[(b0 + 1) * HID + j] = hoB;
    }
}

// ---------------- FC head ----------------
__global__ void fc_k(const float* __restrict__ hn, const float* __restrict__ w1,
                     const float* __restrict__ b1v, const float* __restrict__ w2,
                     const float* __restrict__ b2v, float* __restrict__ out) {
    __shared__ float red[256];
    int b = blockIdx.x, tid = threadIdx.x;
    float part = 0.f;
    if (tid < HID) {
        float acc = 0.f;
        const float* hr = hn + b * HID;
        const float* wrw = w1 + tid * HID;
        for (int k = 0; k < HID; k++) acc = fmaf(wrw[k], hr[k], acc);
        float z = fmaxf(acc + b1v[tid], 0.f);
        part = z * w2[tid];
    }
    red[tid] = part;
    __syncthreads();
    for (int s = 128; s > 0; s >>= 1) {
        if (tid < s) red[tid] += red[tid + s];
        __syncthreads();
    }
    if (tid == 0) out[b] = red[0] + b2v[0];
}

// ---------------- launch ----------------
extern "C" void kernel_launch(void* const* d_in, const int* in_sizes, int n_in,
                              void* d_out, int out_size) {
    const int* x   = (const int*)d_in[0];
    const int* len = (const int*)d_in[1];
    const float* emb = (const float*)d_in[2];
    const float *Wih[4], *Whh[4], *bih[4], *bhh[4];
    for (int l = 0; l < 4; l++) {
        Wih[l] = (const float*)d_in[3 + 4 * l];
        Whh[l] = (const float*)d_in[4 + 4 * l];
        bih[l] = (const float*)d_in[5 + 4 * l];
        bhh[l] = (const float*)d_in[6 + 4 * l];
    }
    const float* fc1w = (const float*)d_in[19];
    const float* fc1b = (const float*)d_in[20];
    const float* fc2w = (const float*)d_in[21];
    const float* fc2b = (const float*)d_in[22];
    float* out = (float*)d_out;

    float *pe, *pxp, *psa, *psb, *phn;
    cudaGetSymbolAddress((void**)&pe,  g_e);
    cudaGetSymbolAddress((void**)&pxp, g_xp);
    cudaGetSymbolAddress((void**)&psa, g_sa);
    cudaGetSymbolAddress((void**)&psb, g_sb);
    cudaGetSymbolAddress((void**)&phn, g_hn);

    const int SMEM = (600 * SMW + 4 * HS + 2 * PS) * 4;  // 224448 B
    cudaFuncSetAttribute(lstm_k, cudaFuncAttributeMaxDynamicSharedMemorySize, SMEM);

    // launch order matters for ncu (-s 5 -c 1): index 5 must be lstm_k (steady state K=150)
    align_k<<<1, 128>>>();                                      // idx 0
    embed_k<<<38400, 256>>>(x, emb);                            // idx 1

    dim3 gg(1024, 5);
    gemm_xproj<<<gg, 256>>>(pe,  EMBD, Wih[0], bih[0], bhh[0], pxp);   // idx 2
    lstm_k<<<128, 320, SMEM>>>(pxp, Whh[0], len, psa, phn);            // idx 3

    gemm_xproj<<<gg, 256>>>(psa, HID,  Wih[1], bih[1], bhh[1], pxp);   // idx 4
    lstm_k<<<128, 320, SMEM>>>(pxp, Whh[1], len, psb, phn);            // idx 5  <- profiled

    gemm_xproj<<<gg, 256>>>(psb, HID,  Wih[2], bih[2], bhh[2], pxp);
    lstm_k<<<128, 320, SMEM>>>(pxp, Whh[2], len, psa, phn);

    gemm_xproj<<<gg, 256>>>(psa, HID,  Wih[3], bih[3], bhh[3], pxp);
    lstm_k<<<128, 320, SMEM>>>(pxp, Whh[3], len, psb, phn);

    fc_k<<<256, 256>>>(phn, fc1w, fc1b, fc2w, fc2b, out);
}

// round 11
// speedup vs baseline: 1.1368x; 1.0383x over previous
#include <cuda_runtime.h>
#include <math.h>

typedef unsigned long long ull;

#define BATCH 256
#define SEQT  512
#define EMBD  300
#define HID   150
#define G4    600   // 4*HID
#define SMW   92    // Whh cols in smem (lane stride 92 words -> conflict-free LDS.128)
#define HS    152   // padded h stride (16B-aligned)

#define FMA2(d, a, b) asm("fma.rn.f32x2 %0, %1, %2, %3;" : "=l"(d) : "l"(a), "l"(b), "l"(d))

__device__ __forceinline__ float sig_f(float x)  { return __fdividef(1.f, 1.f + __expf(-x)); }
__device__ __forceinline__ float tanh_f(float x) { return 1.f - __fdividef(2.f, __expf(2.f * x) + 1.f); }

// ---------------- scratch (static device globals; no allocation) ----------------
__device__ float g_e [(size_t)BATCH*SEQT*EMBD];
__device__ float g_xp[(size_t)BATCH*SEQT*G4];
__device__ float g_sa[(size_t)BATCH*SEQT*HID];
__device__ float g_sb[(size_t)BATCH*SEQT*HID];
__device__ float g_hn[BATCH*HID];

// ---------------- profiling-alignment dummy (keeps ncu -s 5 window on lstm_k) ----------------
__global__ void align_k() {
    if (threadIdx.x < HID) g_hn[threadIdx.x] = 0.f;   // overwritten by lstm_k later
}

// ---------------- embedding gather (x is int32 on device) ----------------
__global__ void embed_k(const int* __restrict__ x, const float* __restrict__ emb) {
    int idx = blockIdx.x * blockDim.x + threadIdx.x;
    const int total = BATCH * SEQT * (EMBD / 4);
    if (idx >= total) return;
    int bt = idx / (EMBD / 4);
    int d4 = (idx - bt * (EMBD / 4)) * 4;
    int row = x[bt];
    const float4 v = *(const float4*)(emb + (size_t)row * EMBD + d4);
    *(float4*)(g_e + (size_t)bt * EMBD + d4) = v;
}

// ---------------- x-projection GEMM (round-5 version: best measured) ----------------
__global__ void __launch_bounds__(256) gemm_xproj(
    const float* __restrict__ A, int K,
    const float* __restrict__ W,
    const float* __restrict__ b1,
    const float* __restrict__ b2,
    float* __restrict__ C) {
    __shared__ float As[16][132];
    __shared__ float Bs[16][132];
    const int tid = threadIdx.x;
    const int m0 = blockIdx.x * 128, n0 = blockIdx.y * 128;
    const int tx = tid & 15, ty = tid >> 4;
    const int lr = tid >> 1, lk = (tid & 1) * 8;

    ull acc2[8][4];
#pragma unroll
    for (int i = 0; i < 8; i++)
#pragma unroll
        for (int j = 0; j < 4; j++) acc2[i][j] = 0ull;

    const float* Ap = A + (size_t)(m0 + lr) * K;
    const int nrow = n0 + lr;
    const float* Wp = W + (size_t)nrow * K;
    const bool wok = nrow < G4;
    const int nt = (K + 15) / 16;

    for (int kt = 0; kt < nt; kt++) {
        const int k0 = kt * 16;
#pragma unroll
        for (int c = 0; c < 4; c++) {
            int k = k0 + lk + 2 * c;
            float2 av = (k < K) ? *(const float2*)(Ap + k) : make_float2(0.f, 0.f);
            float2 wv = (wok && k < K) ? *(const float2*)(Wp + k) : make_float2(0.f, 0.f);
            As[lk + 2 * c][lr]     = av.x;
            As[lk + 2 * c + 1][lr] = av.y;
            Bs[lk + 2 * c][lr]     = wv.x;
            Bs[lk + 2 * c + 1][lr] = wv.y;
        }
        __syncthreads();
#pragma unroll
        for (int kk = 0; kk < 16; kk++) {
            float4 al = *(const float4*)&As[kk][ty * 4];
            float4 ah = *(const float4*)&As[kk][64 + ty * 4];
            ulonglong2 bl = *(const ulonglong2*)&Bs[kk][tx * 4];
            ulonglong2 bh = *(const ulonglong2*)&Bs[kk][64 + tx * 4];
            float a_s[8] = {al.x, al.y, al.z, al.w, ah.x, ah.y, ah.z, ah.w};
#pragma unroll
            for (int i = 0; i < 8; i++) {
                float2 t = make_float2(a_s[i], a_s[i]);
                ull ad = *(ull*)&t;
                FMA2(acc2[i][0], ad, bl.x);
                FMA2(acc2[i][1], ad, bl.y);
                FMA2(acc2[i][2], ad, bh.x);
                FMA2(acc2[i][3], ad, bh.y);
            }
        }
        __syncthreads();
    }
#pragma unroll
    for (int i = 0; i < 8; i++) {
        int m = m0 + ((i < 4) ? ty * 4 + i : 64 + ty * 4 + (i - 4));
        float* Cr = C + (size_t)m * G4;
#pragma unroll
        for (int j2 = 0; j2 < 4; j2++) {
            float2 p = *(float2*)&acc2[i][j2];
            int nn = n0 + ((j2 < 2) ? tx * 4 + 2 * j2 : 64 + tx * 4 + 2 * (j2 - 2));
            if (nn < G4)     Cr[nn]     = p.x + b1[nn]     + b2[nn];
            if (nn + 1 < G4) Cr[nn + 1] = p.y + b1[nn + 1] + b2[nn + 1];
        }
    }
}

// ---------------- LSTM layer: ONE CTA per 2 batches, 320 threads, lane-paired gates ----------------
// tid = 2j+q (j<150): q=0 lane owns rows {j (i), 300+j (g)}, q=1 lane owns {150+j (f), 450+j (o)},
// both batches. i*g crosses even->odd via shfl.xor(1): ONE barrier per step.
// W smem re-laid by R=2j+q (lane stride 92 words, conflict-free); cols [92,150) in 2x29 u64 regs.
__global__ void __launch_bounds__(320, 1) lstm_k(
    const float* __restrict__ xp, const float* __restrict__ Whh,
    const int* __restrict__ lengths,
    float* __restrict__ seq_out, float* __restrict__ hn_out)
{
    extern __shared__ float sm[];
    float* Wif  = sm;                    // 300 x SMW : R=2j+q -> Whh row q*150+j
    float* Wgo  = Wif + 300 * SMW;       // 300 x SMW : R=2j+q -> Whh row 300+q*150+j
    float* hbuf = Wgo + 300 * SMW;       // 2 buffers x 2 batches x HS

    const int tid = threadIdx.x;
    const int b0  = blockIdx.x * 2;
    const int j   = tid >> 1;
    const int q   = tid & 1;
    const bool on = (tid < 300);

    // load W into smem with lane-pair layout
    for (int idx = tid; idx < 600 * SMW; idx += 320) {
        int R = idx / SMW, k = idx - R * SMW;
        int src;
        if (R < 300) { int jj = R >> 1, qq = R & 1; src = qq * 150 + jj; }
        else         { int R2 = R - 300; int jj = R2 >> 1, qq = R2 & 1; src = 300 + qq * 150 + jj; }
        sm[idx] = Whh[(size_t)src * 150 + k];
    }
    for (int idx = tid; idx < 4 * HS; idx += 320) hbuf[idx] = 0.f;

    const int row0 = q * 150 + (on ? j : 0);   // i or f
    const int row1 = row0 + 300;               // g or o
    ull w0r[29], w1r[29];
    {
        const float* g0 = Whh + (size_t)row0 * 150 + SMW;
        const float* g1 = Whh + (size_t)row1 * 150 + SMW;
#pragma unroll
        for (int i = 0; i < 29; i++) {
            w0r[i] = on ? *(const ull*)(g0 + 2 * i) : 0ull;
            w1r[i] = on ? *(const ull*)(g1 + 2 * i) : 0ull;
        }
    }
    // CLAMPED for inactive tail threads (tid>=300): they still execute the dot
    // product (to reach the shfl), so their smem W rows must stay in-bounds.
    const int rr = on ? tid : 0;
    const float* wp0 = Wif + rr * SMW;
    const float* wp1 = Wgo + rr * SMW;

    const float* xA = xp + ((size_t)b0 * SEQT) * G4;
    const float* xB = xp + ((size_t)(b0 + 1) * SEQT) * G4;

    const int lenA = lengths[b0], lenB = lengths[b0 + 1];
    float cAr = 0.f, cBr = 0.f, hoA = 0.f, hoB = 0.f;   // odd-lane private state

    // prefetch xg for t=0
    float x0A = 0.f, x1A = 0.f, x0B = 0.f, x1B = 0.f;
    if (on) {
        x0A = xA[row0]; x1A = xA[row1];
        x0B = xB[row0]; x1B = xB[row1];
    }
    __syncthreads();

    for (int t = 0; t < SEQT; t++) {
        const float* hR = hbuf + (t & 1) * (2 * HS);
        float* hW = hbuf + ((t + 1) & 1) * (2 * HS);

        ull a00 = 0ull, a01 = 0ull, a10 = 0ull, a11 = 0ull;  // (row, batch)
#pragma unroll
        for (int g = 0; g < 23; g++) {
            const int k = 4 * g;
            ulonglong2 hA2 = *(const ulonglong2*)(hR + k);
            ulonglong2 hB2 = *(const ulonglong2*)(hR + HS + k);
            ulonglong2 w0 = *(const ulonglong2*)(wp0 + k);
            ulonglong2 w1 = *(const ulonglong2*)(wp1 + k);
            FMA2(a00, w0.x, hA2.x); FMA2(a00, w0.y, hA2.y);
            FMA2(a01, w0.x, hB2.x); FMA2(a01, w0.y, hB2.y);
            FMA2(a10, w1.x, hA2.x); FMA2(a10, w1.y, hA2.y);
            FMA2(a11, w1.x, hB2.x); FMA2(a11, w1.y, hB2.y);
        }
#pragma unroll
        for (int c = 0; c < 14; c++) {
            const int k = SMW + 4 * c;
            ulonglong2 hA2 = *(const ulonglong2*)(hR + k);
            ulonglong2 hB2 = *(const ulonglong2*)(hR + HS + k);
            FMA2(a00, w0r[2 * c], hA2.x); FMA2(a00, w0r[2 * c + 1], hA2.y);
            FMA2(a01, w0r[2 * c], hB2.x); FMA2(a01, w0r[2 * c + 1], hB2.y);
            FMA2(a10, w1r[2 * c], hA2.x); FMA2(a10, w1r[2 * c + 1], hA2.y);
            FMA2(a11, w1r[2 * c], hB2.x); FMA2(a11, w1r[2 * c + 1], hB2.y);
        }
        {   // cols 148,149
            ull hA1 = *(const ull*)(hR + 148);
            ull hB1 = *(const ull*)(hR + HS + 148);
            FMA2(a00, w0r[28], hA1); FMA2(a01, w0r[28], hB1);
            FMA2(a10, w1r[28], hA1); FMA2(a11, w1r[28], hB1);
        }
        float2 f00 = *(float2*)&a00, f01 = *(float2*)&a01;
        float2 f10 = *(float2*)&a10, f11 = *(float2*)&a11;
        float pre0A = f00.x + f00.y + x0A;   // i (even) / f (odd)
        float pre0B = f01.x + f01.y + x0B;
        float pre1A = f10.x + f10.y + x1A;   // g (even) / o (odd)
        float pre1B = f11.x + f11.y + x1B;

        if (on && t + 1 < SEQT) {   // prefetch next xg
            const size_t o = (size_t)(t + 1) * G4;
            x0A = xA[o + row0]; x1A = xA[o + row1];
            x0B = xB[o + row0]; x1B = xB[o + row1];
        }

        float s0A = sig_f(pre0A), s0B = sig_f(pre0B);                         // i or f
        float v1A = (q == 0) ? tanh_f(pre1A) : sig_f(pre1A);                  // g or o
        float v1B = (q == 0) ? tanh_f(pre1B) : sig_f(pre1B);
        float prodA = s0A * v1A;   // even lanes: i*g
        float prodB = s0B * v1B;
        float pA = __shfl_xor_sync(0xffffffffu, prodA, 1);   // odd gets even's i*g
        float pB = __shfl_xor_sync(0xffffffffu, prodB, 1);

        if (on && q == 1) {
            float cnA = fmaf(s0A, cAr, pA);     // f*c + i*g
            float cnB = fmaf(s0B, cBr, pB);
            float hvA = v1A * tanh_f(cnA);      // o * tanh(c)
            float hvB = v1B * tanh_f(cnB);
            bool mA = t < lenA, mB = t < lenB;
            seq_out[((size_t)b0 * SEQT + t) * HID + j]       = mA ? hvA : 0.f;
            seq_out[((size_t)(b0 + 1) * SEQT + t) * HID + j] = mB ? hvB : 0.f;
            if (mA) { cAr = cnA; hoA = hvA; }
            if (mB) { cBr = cnB; hoB = hvB; }
            hW[j]      = hoA;
            hW[HS + j] = hoB;
        }
        __syncthreads();
    }

    if (on && q == 1) {
        hn_out[b0 * HID + j]       = hoA;
        hn_out[(b0 + 1) * HID + j] = hoB;
    }
}

// ---------------- FC head ----------------
__global__ void fc_k(const float* __restrict__ hn, const float* __restrict__ w1,
                     const float* __restrict__ b1v, const float* __restrict__ w2,
                     const float* __restrict__ b2v, float* __restrict__ out) {
    __shared__ float red[256];
    int b = blockIdx.x, tid = threadIdx.x;
    float part = 0.f;
    if (tid < HID) {
        float acc = 0.f;
        const float* hr = hn + b * HID;
        const float* wrw = w1 + tid * HID;
        for (int k = 0; k < HID; k++) acc = fmaf(wrw[k], hr[k], acc);
        float z = fmaxf(acc + b1v[tid], 0.f);
        part = z * w2[tid];
    }
    red[tid] = part;
    __syncthreads();
    for (int s = 128; s > 0; s >>= 1) {
        if (tid < s) red[tid] += red[tid + s];
        __syncthreads();
    }
    if (tid == 0) out[b] = red[0] + b2v[0];
}

// ---------------- launch ----------------
extern "C" void kernel_launch(void* const* d_in, const int* in_sizes, int n_in,
                              void* d_out, int out_size) {
    const int* x   = (const int*)d_in[0];
    const int* len = (const int*)d_in[1];
    const float* emb = (const float*)d_in[2];
    const float *Wih[4], *Whh[4], *bih[4], *bhh[4];
    for (int l = 0; l < 4; l++) {
        Wih[l] = (const float*)d_in[3 + 4 * l];
        Whh[l] = (const float*)d_in[4 + 4 * l];
        bih[l] = (const float*)d_in[5 + 4 * l];
        bhh[l] = (const float*)d_in[6 + 4 * l];
    }
    const float* fc1w = (const float*)d_in[19];
    const float* fc1b = (const float*)d_in[20];
    const float* fc2w = (const float*)d_in[21];
    const float* fc2b = (const float*)d_in[22];
    float* out = (float*)d_out;

    float *pe, *pxp, *psa, *psb, *phn;
    cudaGetSymbolAddress((void**)&pe,  g_e);
    cudaGetSymbolAddress((void**)&pxp, g_xp);
    cudaGetSymbolAddress((void**)&psa, g_sa);
    cudaGetSymbolAddress((void**)&psb, g_sb);
    cudaGetSymbolAddress((void**)&phn, g_hn);

    const int SMEM = (600 * SMW + 4 * HS) * 4;  // 223232 B
    cudaFuncSetAttribute(lstm_k, cudaFuncAttributeMaxDynamicSharedMemorySize, SMEM);

    // launch order matters for ncu (-s 5 -c 1): index 5 must be lstm_k (steady state K=150)
    align_k<<<1, 128>>>();                                      // idx 0
    embed_k<<<38400, 256>>>(x, emb);                            // idx 1

    dim3 gg(1024, 5);
    gemm_xproj<<<gg, 256>>>(pe,  EMBD, Wih[0], bih[0], bhh[0], pxp);   // idx 2
    lstm_k<<<128, 320, SMEM>>>(pxp, Whh[0], len, psa, phn);            // idx 3

    gemm_xproj<<<gg, 256>>>(psa, HID,  Wih[1], bih[1], bhh[1], pxp);   // idx 4
    lstm_k<<<128, 320, SMEM>>>(pxp, Whh[1], len, psb, phn);            // idx 5  <- profiled

    gemm_xproj<<<gg, 256>>>(psb, HID,  Wih[2], bih[2], bhh[2], pxp);
    lstm_k<<<128, 320, SMEM>>>(pxp, Whh[2], len, psa, phn);

    gemm_xproj<<<gg, 256>>>(psa, HID,  Wih[3], bih[3], bhh[3], pxp);
    lstm_k<<<128, 320, SMEM>>>(pxp, Whh[3], len, psb, phn);

    fc_k<<<256, 256>>>(phn, fc1w, fc1b, fc2w, fc2b, out);
}

// round 12
// speedup vs baseline: 1.1580x; 1.0187x over previous
#include <cuda_runtime.h>
#include <math.h>

typedef unsigned long long ull;

#define BATCH 256
#define SEQT  512
#define EMBD  300
#define HID   150
#define G4    600   // 4*HID
#define HS    152   // padded h stride (16B-aligned)
#define NW2   46    // W smem pair-rows per thread (2 rows x 23 pairs)
#define TSTR  608   // SoA tid stride

#define FMA2(d, a, b) asm("fma.rn.f32x2 %0, %1, %2, %3;" : "=l"(d) : "l"(a), "l"(b), "l"(d))

__device__ __forceinline__ float sig_f(float x)  { return __fdividef(1.f, 1.f + __expf(-x)); }
__device__ __forceinline__ float tanh_f(float x) { return 1.f - __fdividef(2.f, __expf(2.f * x) + 1.f); }

// ---------------- scratch (static device globals; no allocation) ----------------
__device__ float g_e [(size_t)BATCH*SEQT*EMBD];
__device__ float g_xp[(size_t)BATCH*SEQT*G4];
__device__ float g_sa[(size_t)BATCH*SEQT*HID];
__device__ float g_sb[(size_t)BATCH*SEQT*HID];
__device__ float g_hn[BATCH*HID];

// ---------------- profiling-alignment dummy (keeps ncu -s 5 window on lstm_k) ----------------
__global__ void align_k() {
    if (threadIdx.x < HID) g_hn[threadIdx.x] = 0.f;   // overwritten by lstm_k later
}

// ---------------- embedding gather (x is int32 on device) ----------------
__global__ void embed_k(const int* __restrict__ x, const float* __restrict__ emb) {
    int idx = blockIdx.x * blockDim.x + threadIdx.x;
    const int total = BATCH * SEQT * (EMBD / 4);
    if (idx >= total) return;
    int bt = idx / (EMBD / 4);
    int d4 = (idx - bt * (EMBD / 4)) * 4;
    int row = x[bt];
    const float4 v = *(const float4*)(emb + (size_t)row * EMBD + d4);
    *(float4*)(g_e + (size_t)bt * EMBD + d4) = v;
}

// ---------------- x-projection GEMM (round-5 version: best measured) ----------------
__global__ void __launch_bounds__(256) gemm_xproj(
    const float* __restrict__ A, int K,
    const float* __restrict__ W,
    const float* __restrict__ b1,
    const float* __restrict__ b2,
    float* __restrict__ C) {
    __shared__ float As[16][132];
    __shared__ float Bs[16][132];
    const int tid = threadIdx.x;
    const int m0 = blockIdx.x * 128, n0 = blockIdx.y * 128;
    const int tx = tid & 15, ty = tid >> 4;
    const int lr = tid >> 1, lk = (tid & 1) * 8;

    ull acc2[8][4];
#pragma unroll
    for (int i = 0; i < 8; i++)
#pragma unroll
        for (int j = 0; j < 4; j++) acc2[i][j] = 0ull;

    const float* Ap = A + (size_t)(m0 + lr) * K;
    const int nrow = n0 + lr;
    const float* Wp = W + (size_t)nrow * K;
    const bool wok = nrow < G4;
    const int nt = (K + 15) / 16;

    for (int kt = 0; kt < nt; kt++) {
        const int k0 = kt * 16;
#pragma unroll
        for (int c = 0; c < 4; c++) {
            int k = k0 + lk + 2 * c;
            float2 av = (k < K) ? *(const float2*)(Ap + k) : make_float2(0.f, 0.f);
            float2 wv = (wok && k < K) ? *(const float2*)(Wp + k) : make_float2(0.f, 0.f);
            As[lk + 2 * c][lr]     = av.x;
            As[lk + 2 * c + 1][lr] = av.y;
            Bs[lk + 2 * c][lr]     = wv.x;
            Bs[lk + 2 * c + 1][lr] = wv.y;
        }
        __syncthreads();
#pragma unroll
        for (int kk = 0; kk < 16; kk++) {
            float4 al = *(const float4*)&As[kk][ty * 4];
            float4 ah = *(const float4*)&As[kk][64 + ty * 4];
            ulonglong2 bl = *(const ulonglong2*)&Bs[kk][tx * 4];
            ulonglong2 bh = *(const ulonglong2*)&Bs[kk][64 + tx * 4];
            float a_s[8] = {al.x, al.y, al.z, al.w, ah.x, ah.y, ah.z, ah.w};
#pragma unroll
            for (int i = 0; i < 8; i++) {
                float2 t = make_float2(a_s[i], a_s[i]);
                ull ad = *(ull*)&t;
                FMA2(acc2[i][0], ad, bl.x);
                FMA2(acc2[i][1], ad, bl.y);
                FMA2(acc2[i][2], ad, bh.x);
                FMA2(acc2[i][3], ad, bh.y);
            }
        }
        __syncthreads();
    }
#pragma unroll
    for (int i = 0; i < 8; i++) {
        int m = m0 + ((i < 4) ? ty * 4 + i : 64 + ty * 4 + (i - 4));
        float* Cr = C + (size_t)m * G4;
#pragma unroll
        for (int j2 = 0; j2 < 4; j2++) {
            float2 p = *(float2*)&acc2[i][j2];
            int nn = n0 + ((j2 < 2) ? tx * 4 + 2 * j2 : 64 + tx * 4 + 2 * (j2 - 2));
            if (nn < G4)     Cr[nn]     = p.x + b1[nn]     + b2[nn];
            if (nn + 1 < G4) Cr[nn + 1] = p.y + b1[nn + 1] + b2[nn + 1];
        }
    }
}

// ---------------- LSTM layer: ONE CTA per 2 batches, 608 threads, k-split lane quads ----------------
// tid = 4j+2q+s: j = hidden unit, q = gate pair (0: i&g, 1: f&o), s = k-half (parity-interleaved
// 16B chunks). W smem cols [0,92) stored SoA (W2[p][tid], 2wf coalesced reads); cols [92,150)
// in 14 u64 + 1 f32 regs per row. k-halves merge via shfl.xor(1); i*g -> f&o lane via shfl.xor(2).
__global__ void __launch_bounds__(608, 1) lstm_k(
    const float* __restrict__ xp, const float* __restrict__ Whh,
    const int* __restrict__ lengths,
    float* __restrict__ seq_out, float* __restrict__ hn_out, int write_seq)
{
    extern __shared__ float sm[];
    ull*   W2   = (ull*)sm;                 // NW2 x TSTR ull (223744 B)
    float* hbuf = sm + NW2 * TSTR * 2;      // 2 buffers x 2 batches x HS

    const int tid = threadIdx.x;
    const int b0  = blockIdx.x * 2;
    const int j   = tid >> 2;
    const int q   = (tid >> 1) & 1;
    const int s   = tid & 1;
    const bool on = (tid < 600);
    const int jc  = on ? j : 0;
    const int row0 = q * 150 + jc;          // i (q=0) or f (q=1)
    const int row1 = row0 + 300;            // g or o

    // init: each thread fills its own SoA column (46 pairs = 2 rows x 23 pairs)
    for (int p = 0; p < NW2; p++) {
        int pr  = (p < 23) ? p : p - 23;
        int row = (p < 23) ? row0 : row1;
        int col = (pr < 22) ? (8 * (pr >> 1) + 4 * s + 2 * (pr & 1)) : (88 + 2 * s);
        W2[p * TSTR + tid] = *(const ull*)(Whh + (size_t)row * 150 + col);
    }
    for (int idx = tid; idx < 4 * HS; idx += 608) hbuf[idx] = 0.f;

    // register W: cols 92..147 parity chunks (14 u64 per row) + tail col 148+s
    ull w0r[14], w1r[14];
    float w0t, w1t;
    {
        const int cb = 96 - 4 * s;   // s=0 -> chunks 24,26,..; s=1 -> 23,25,..
#pragma unroll
        for (int r = 0; r < 14; r++) {
            int col = cb + 8 * (r >> 1) + 2 * (r & 1);
            w0r[r] = *(const ull*)(Whh + (size_t)row0 * 150 + col);
            w1r[r] = *(const ull*)(Whh + (size_t)row1 * 150 + col);
        }
        w0t = Whh[(size_t)row0 * 150 + 148 + s];
        w1t = Whh[(size_t)row1 * 150 + 148 + s];
    }

    const float* xAb = xp + (size_t)b0 * SEQT * G4;
    const float* xBb = xAb + (size_t)SEQT * G4;
    const int lenA = lengths[b0], lenB = lengths[b0 + 1];
    float cA = 0.f, cB = 0.f, hoA = 0.f, hoB = 0.f;   // writer-lane private state

    __syncthreads();

    for (int t = 0; t < SEQT; t++) {
        const float* hR = hbuf + (t & 1) * (2 * HS);
        float* hW = hbuf + ((t + 1) & 1) * (2 * HS);

        // x loads issued early (hidden under the dot product)
        float xv00 = 0.f, xv01 = 0.f, xv10 = 0.f, xv11 = 0.f;
        if (s == 0 && on) {
            const size_t o = (size_t)t * G4;
            xv00 = xAb[o + row0]; xv01 = xBb[o + row0];
            xv10 = xAb[o + row1]; xv11 = xBb[o + row1];
        }

        ull a00 = 0ull, a01 = 0ull, a10 = 0ull, a11 = 0ull;   // (row, batch)
        const ull* Wl = W2 + tid;
        const float* hRs = hR + 4 * s;
#pragma unroll
        for (int p = 0; p < 22; p++) {
            const int cb = 8 * (p >> 1) + 2 * (p & 1);
            ull w0 = Wl[p * TSTR];
            ull w1 = Wl[(23 + p) * TSTR];
            ull hA = *(const ull*)(hRs + cb);
            ull hB = *(const ull*)(hRs + HS + cb);
            FMA2(a00, w0, hA); FMA2(a01, w0, hB);
            FMA2(a10, w1, hA); FMA2(a11, w1, hB);
        }
        {   // p = 22: cols 88+2s
            ull w0 = Wl[22 * TSTR];
            ull w1 = Wl[45 * TSTR];
            const float* ht = hR + 88 + 2 * s;
            ull hA = *(const ull*)ht;
            ull hB = *(const ull*)(ht + HS);
            FMA2(a00, w0, hA); FMA2(a01, w0, hB);
            FMA2(a10, w1, hA); FMA2(a11, w1, hB);
        }
        {   // register cols 92..147 (parity chunks)
            const float* hq = hR + (96 - 4 * s);
#pragma unroll
            for (int r = 0; r < 14; r++) {
                const int d = 8 * (r >> 1) + 2 * (r & 1);
                ull hA = *(const ull*)(hq + d);
                ull hB = *(const ull*)(hq + HS + d);
                FMA2(a00, w0r[r], hA); FMA2(a01, w0r[r], hB);
                FMA2(a10, w1r[r], hA); FMA2(a11, w1r[r], hB);
            }
        }
        // tail col 148+s (scalar)
        float htA = hR[148 + s], htB = hR[HS + 148 + s];
        float2 f00 = *(float2*)&a00, f01 = *(float2*)&a01;
        float2 f10 = *(float2*)&a10, f11 = *(float2*)&a11;
        float d00 = f00.x + f00.y + w0t * htA + xv00;
        float d01 = f01.x + f01.y + w0t * htB + xv01;
        float d10 = f10.x + f10.y + w1t * htA + xv10;
        float d11 = f11.x + f11.y + w1t * htB + xv11;

        // merge k-halves (both lanes end with the full pre-activation)
        d00 += __shfl_xor_sync(0xffffffffu, d00, 1);
        d01 += __shfl_xor_sync(0xffffffffu, d01, 1);
        d10 += __shfl_xor_sync(0xffffffffu, d10, 1);
        d11 += __shfl_xor_sync(0xffffffffu, d11, 1);

        float v0A = sig_f(d00), v0B = sig_f(d01);                       // i or f
        float v1A = (q == 0) ? tanh_f(d10) : sig_f(d10);                // g or o
        float v1B = (q == 0) ? tanh_f(d11) : sig_f(d11);

        float pA = __shfl_xor_sync(0xffffffffu, v0A * v1A, 2);          // i*g -> q=1 lanes
        float pB = __shfl_xor_sync(0xffffffffu, v0B * v1B, 2);

        if (on && q == 1 && s == 0) {
            float cnA = fmaf(v0A, cA, pA);      // f*c + i*g
            float cnB = fmaf(v0B, cB, pB);
            float hvA = v1A * tanh_f(cnA);      // o * tanh(c)
            float hvB = v1B * tanh_f(cnB);
            bool mA = t < lenA, mB = t < lenB;
            if (write_seq) {
                seq_out[((size_t)b0 * SEQT + t) * HID + j]       = mA ? hvA : 0.f;
                seq_out[((size_t)(b0 + 1) * SEQT + t) * HID + j] = mB ? hvB : 0.f;
            }
            if (mA) { cA = cnA; hoA = hvA; }
            if (mB) { cB = cnB; hoB = hvB; }
            hW[j]      = hoA;
            hW[HS + j] = hoB;
        }
        __syncthreads();
    }

    if (on && q == 1 && s == 0) {
        hn_out[b0 * HID + j]       = hoA;
        hn_out[(b0 + 1) * HID + j] = hoB;
    }
}

// ---------------- FC head ----------------
__global__ void fc_k(const float* __restrict__ hn, const float* __restrict__ w1,
                     const float* __restrict__ b1v, const float* __restrict__ w2,
                     const float* __restrict__ b2v, float* __restrict__ out) {
    __shared__ float red[256];
    int b = blockIdx.x, tid = threadIdx.x;
    float part = 0.f;
    if (tid < HID) {
        float acc = 0.f;
        const float* hr = hn + b * HID;
        const float* wrw = w1 + tid * HID;
        for (int k = 0; k < HID; k++) acc = fmaf(wrw[k], hr[k], acc);
        float z = fmaxf(acc + b1v[tid], 0.f);
        part = z * w2[tid];
    }
    red[tid] = part;
    __syncthreads();
    for (int s = 128; s > 0; s >>= 1) {
        if (tid < s) red[tid] += red[tid + s];
        __syncthreads();
    }
    if (tid == 0) out[b] = red[0] + b2v[0];
}

// ---------------- launch ----------------
extern "C" void kernel_launch(void* const* d_in, const int* in_sizes, int n_in,
                              void* d_out, int out_size) {
    const int* x   = (const int*)d_in[0];
    const int* len = (const int*)d_in[1];
    const float* emb = (const float*)d_in[2];
    const float *Wih[4], *Whh[4], *bih[4], *bhh[4];
    for (int l = 0; l < 4; l++) {
        Wih[l] = (const float*)d_in[3 + 4 * l];
        Whh[l] = (const float*)d_in[4 + 4 * l];
        bih[l] = (const float*)d_in[5 + 4 * l];
        bhh[l] = (const float*)d_in[6 + 4 * l];
    }
    const float* fc1w = (const float*)d_in[19];
    const float* fc1b = (const float*)d_in[20];
    const float* fc2w = (const float*)d_in[21];
    const float* fc2b = (const float*)d_in[22];
    float* out = (float*)d_out;

    float *pe, *pxp, *psa, *psb, *phn;
    cudaGetSymbolAddress((void**)&pe,  g_e);
    cudaGetSymbolAddress((void**)&pxp, g_xp);
    cudaGetSymbolAddress((void**)&psa, g_sa);
    cudaGetSymbolAddress((void**)&psb, g_sb);
    cudaGetSymbolAddress((void**)&phn, g_hn);

    const int SMEM = NW2 * TSTR * 8 + 4 * HS * 4;  // 223744 + 2432 = 226176 B
    cudaFuncSetAttribute(lstm_k, cudaFuncAttributeMaxDynamicSharedMemorySize, SMEM);

    // launch order matters for ncu (-s 5 -c 1): index 5 must be lstm_k (steady state K=150)
    align_k<<<1, 128>>>();                                      // idx 0
    embed_k<<<38400, 256>>>(x, emb);                            // idx 1

    dim3 gg(1024, 5);
    gemm_xproj<<<gg, 256>>>(pe,  EMBD, Wih[0], bih[0], bhh[0], pxp);   // idx 2
    lstm_k<<<128, 608, SMEM>>>(pxp, Whh[0], len, psa, phn, 1);         // idx 3

    gemm_xproj<<<gg, 256>>>(psa, HID,  Wih[1], bih[1], bhh[1], pxp);   // idx 4
    lstm_k<<<128, 608, SMEM>>>(pxp, Whh[1], len, psb, phn, 1);         // idx 5  <- profiled

    gemm_xproj<<<gg, 256>>>(psb, HID,  Wih[2], bih[2], bhh[2], pxp);
    lstm_k<<<128, 608, SMEM>>>(pxp, Whh[2], len, psa, phn, 1);

    gemm_xproj<<<gg, 256>>>(psa, HID,  Wih[3], bih[3], bhh[3], pxp);
    lstm_k<<<128, 608, SMEM>>>(pxp, Whh[3], len, psb, phn, 0);         // hn only

    fc_k<<<256, 256>>>(phn, fc1w, fc1b, fc2w, fc2b, out);
}